// round 9
// baseline (speedup 1.0000x reference)
#include <cuda_runtime.h>
#include <math.h>
#include <stdint.h>

#define NMAX 200704
#define DD 512
#define KCLS 4
#define MP 8
#define JJ 32           // KCLS*MP
#define INV_EPS 20.0f   // 1/0.05
#define GAMMA_M 0.999f

// ---------------- scratch (device globals; no allocations) ----------------
__device__ __align__(16) float gPN[JJ * DD];      // normalized prototypes [j][d]
__device__ __align__(16) float gWmat[DD * JJ];    // W[d][j] = g[d]*pN[j][d]
__device__ __align__(16) float gS1[JJ];
__device__ __align__(16) float gS2[JJ];
__device__ __align__(16) float gCst[4];           // Q0=sum g^2, R0=sum g*b, B2=sum b^2
__device__ __align__(16) float4 gABC[NMAX];       // (a, beta, c, unused) per token
__device__ __align__(16) float gMasksOwn[NMAX * MP];
__device__ unsigned char gPred[NMAX];
__device__ __align__(16) float gC[3][JJ];         // sinkhorn column sums, iters 1..3
__device__ __align__(16) float gBcnt[KCLS];       // per-class selected counts
__device__ __align__(16) float gF[JJ * DD];       // aggregation accumulators
__device__ __align__(16) float gNcnt[JJ];         // per-bucket counts

// ---------------- kernel 1: init (normalize protos, constants, zero scratch) ---
__global__ void initKernel(const float* __restrict__ protos,
                           const float* __restrict__ g,
                           const float* __restrict__ b) {
    int tid = threadIdx.x;
    int w = tid >> 5, l = tid & 31;

    // zero scratch (must happen every graph replay)
    for (int i = tid; i < JJ * DD; i += 1024) gF[i] = 0.f;
    if (tid < 3 * JJ) ((float*)gC)[tid] = 0.f;
    if (tid < JJ) gNcnt[tid] = 0.f;
    if (tid < KCLS) gBcnt[tid] = 0.f;

    // warp w normalizes prototype row w (j = k*8+m)
    {
        const float* p = protos + (size_t)w * DD;
        float v[16];
        float ss = 0.f;
#pragma unroll
        for (int i = 0; i < 16; i++) {
            v[i] = p[l + 32 * i];
            ss += v[i] * v[i];
        }
#pragma unroll
        for (int o = 16; o > 0; o >>= 1) ss += __shfl_xor_sync(0xffffffffu, ss, o);
        float inv = 1.f / fmaxf(sqrtf(ss), 1e-12f);
        float s1 = 0.f, s2 = 0.f;
#pragma unroll
        for (int i = 0; i < 16; i++) {
            int d = l + 32 * i;
            float pn = v[i] * inv;
            float gv = g[d], bv = b[d];
            gPN[w * DD + d] = pn;
            gWmat[d * JJ + w] = gv * pn;
            s1 += gv * pn;
            s2 += bv * pn;
        }
#pragma unroll
        for (int o = 16; o > 0; o >>= 1) {
            s1 += __shfl_xor_sync(0xffffffffu, s1, o);
            s2 += __shfl_xor_sync(0xffffffffu, s2, o);
        }
        if (l == 0) { gS1[w] = s1; gS2[w] = s2; }
    }

    // warp 0: global LN constants
    if (w == 0) {
        float q0 = 0.f, r0 = 0.f, b2 = 0.f;
#pragma unroll
        for (int i = 0; i < 16; i++) {
            int d = l + 32 * i;
            float gv = g[d], bv = b[d];
            q0 += gv * gv;
            r0 += gv * bv;
            b2 += bv * bv;
        }
#pragma unroll
        for (int o = 16; o > 0; o >>= 1) {
            q0 += __shfl_xor_sync(0xffffffffu, q0, o);
            r0 += __shfl_xor_sync(0xffffffffu, r0, o);
            b2 += __shfl_xor_sync(0xffffffffu, b2, o);
        }
        if (l == 0) { gCst[0] = q0; gCst[1] = r0; gCst[2] = b2; gCst[3] = 0.f; }
    }
}

// ---------------- kernel 2: per-token LN/L2 stats -> (a, beta, c) --------------
__global__ void __launch_bounds__(256) statsKernel(const float* __restrict__ X,
                                                   const float* __restrict__ g,
                                                   const float* __restrict__ b,
                                                   int n) {
    int l = threadIdx.x & 31;
    int wid = (blockIdx.x * blockDim.x + threadIdx.x) >> 5;
    int nw = (gridDim.x * blockDim.x) >> 5;
    float Q0 = gCst[0], R0 = gCst[1], B2 = gCst[2];

    for (int tok = wid; tok < n; tok += nw) {
        const float* x = X + (size_t)tok * DD;
        float sx = 0.f, sxx = 0.f, q2 = 0.f, q1 = 0.f, r1 = 0.f;
#pragma unroll
        for (int i = 0; i < 16; i++) {
            int d = l + 32 * i;
            float xv = x[d];
            float gv = g[d], bv = b[d];
            float gg = gv * gv;
            float x2 = xv * xv;
            sx += xv;
            sxx += x2;
            q2 += x2 * gg;
            q1 += xv * gg;
            r1 += xv * gv * bv;
        }
#pragma unroll
        for (int o = 16; o > 0; o >>= 1) {
            sx  += __shfl_xor_sync(0xffffffffu, sx,  o);
            sxx += __shfl_xor_sync(0xffffffffu, sxx, o);
            q2  += __shfl_xor_sync(0xffffffffu, q2,  o);
            q1  += __shfl_xor_sync(0xffffffffu, q1,  o);
            r1  += __shfl_xor_sync(0xffffffffu, r1,  o);
        }
        if (l == 0) {
            const float invD = 1.f / 512.f;
            float mu = sx * invD;
            float var = sxx * invD - mu * mu;
            float istd = rsqrtf(var + 1e-5f);
            // ||y||^2, y = (x-mu)*istd*g + b
            float ysq = istd * istd * (q2 - 2.f * mu * q1 + mu * mu * Q0)
                      + 2.f * istd * (r1 - mu * R0) + B2;
            float yn = fmaxf(sqrtf(fmaxf(ysq, 0.f)), 1e-12f);
            float inv = 1.f / yn;
            gABC[tok] = make_float4(istd * inv, -istd * mu * inv, inv, 0.f);
        }
    }
}

// ---------------- kernel 3: GEMM [128tok x 32proto] + fused epilogue -----------
__global__ void __launch_bounds__(256) gemmKernel(const float* __restrict__ X,
                                                  const int* __restrict__ gt,
                                                  const float* __restrict__ mg,
                                                  const float* __restrict__ mb,
                                                  float* __restrict__ outseg,
                                                  int n) {
    __shared__ float Xs[128 * 36];   // also reused as masks tile
    __shared__ float Ws[32 * 36];
    __shared__ float S1s[JJ], S2s[JJ];
    __shared__ float Cp[JJ];
    __shared__ float Bp[KCLS];

    int tid = threadIdx.x;
    int jg = tid & 7;        // proto group (4 protos)
    int tg = tid >> 3;       // token group (4 tokens)
    int tokBase = blockIdx.x * 128;

    if (tid < JJ) { S1s[tid] = gS1[tid]; S2s[tid] = gS2[tid]; Cp[tid] = 0.f; }
    if (tid < KCLS) Bp[tid] = 0.f;

    float acc[4][4] = {};

    for (int kc = 0; kc < 512; kc += 32) {
        // stage X chunk [128][32]
#pragma unroll
        for (int r = 0; r < 4; r++) {
            int li = tid + 256 * r;
            int row = li >> 3;
            int c4 = (li & 7) * 4;
            int tok = tokBase + row;
            float4 v = (tok < n)
                ? *(const float4*)(X + (size_t)tok * 512 + kc + c4)
                : make_float4(0.f, 0.f, 0.f, 0.f);
            *(float4*)(Xs + row * 36 + c4) = v;
        }
        // stage W chunk [32][32]
        {
            int row = tid >> 3;
            int c4 = (tid & 7) * 4;
            float4 wv = *(const float4*)(gWmat + (size_t)(kc + row) * 32 + c4);
            *(float4*)(Ws + row * 36 + c4) = wv;
        }
        __syncthreads();
#pragma unroll 8
        for (int k = 0; k < 32; k++) {
            float4 wv = *(const float4*)(Ws + k * 36 + jg * 4);
            float xv[4];
#pragma unroll
            for (int i = 0; i < 4; i++) xv[i] = Xs[(tg * 4 + i) * 36 + k];
#pragma unroll
            for (int i = 0; i < 4; i++) {
                acc[i][0] = fmaf(xv[i], wv.x, acc[i][0]);
                acc[i][1] = fmaf(xv[i], wv.y, acc[i][1]);
                acc[i][2] = fmaf(xv[i], wv.z, acc[i][2]);
                acc[i][3] = fmaf(xv[i], wv.w, acc[i][3]);
            }
        }
        __syncthreads();
    }

    // write accumulators to smem masks tile (reuse Xs)
#pragma unroll
    for (int i = 0; i < 4; i++) {
        float4 v = make_float4(acc[i][0], acc[i][1], acc[i][2], acc[i][3]);
        *(float4*)(Xs + (tg * 4 + i) * 36 + jg * 4) = v;
    }
    __syncthreads();

    // epilogue: one thread per token
    if (tid < 128) {
        int tok = tokBase + tid;
        if (tok < n) {
            float4 abc = gABC[tok];
            float m[32];
            float mx[4];
#pragma unroll
            for (int k = 0; k < 4; k++) {
                float best = -1e30f;
#pragma unroll
                for (int mm = 0; mm < 8; mm++) {
                    int j = k * 8 + mm;
                    float v = abc.x * Xs[tid * 36 + j] + abc.y * S1s[j] + abc.z * S2s[j];
                    m[j] = v;
                    best = fmaxf(best, v);
                }
                mx[k] = best;
            }
            // layer_norm over the 4 maxima (eps=1e-5)
            float mu = 0.25f * (mx[0] + mx[1] + mx[2] + mx[3]);
            float var = 0.f;
#pragma unroll
            for (int k = 0; k < 4; k++) { float d = mx[k] - mu; var += d * d; }
            var *= 0.25f;
            float is4 = 1.f / sqrtf(var + 1e-5f);
            float o[4];
            int pred = 0; float bo = -1e30f;
#pragma unroll
            for (int k = 0; k < 4; k++) {
                o[k] = (mx[k] - mu) * is4 * mg[k] + mb[k];
                if (o[k] > bo) { bo = o[k]; pred = k; }
            }
            *(float4*)(outseg + (size_t)tok * 4) = make_float4(o[0], o[1], o[2], o[3]);
            gPred[tok] = (unsigned char)pred;

            int kk = gt[tok];
            // store own-class scores + accumulate sinkhorn iter-1 column sums
            float mo[8];
#pragma unroll
            for (int mm = 0; mm < 8; mm++) mo[mm] = m[kk * 8 + mm];
            *(float4*)(gMasksOwn + (size_t)tok * 8)     = make_float4(mo[0], mo[1], mo[2], mo[3]);
            *(float4*)(gMasksOwn + (size_t)tok * 8 + 4) = make_float4(mo[4], mo[5], mo[6], mo[7]);
#pragma unroll
            for (int mm = 0; mm < 8; mm++)
                atomicAdd(&Cp[kk * 8 + mm], expf(mo[mm] * INV_EPS));
            atomicAdd(&Bp[kk], 1.f);
        }
    }
    __syncthreads();
    if (tid < JJ && Cp[tid] != 0.f) atomicAdd(&gC[0][tid], Cp[tid]);
    if (tid < KCLS && Bp[tid] != 0.f) atomicAdd(&gBcnt[tid], Bp[tid]);
}

// ---------------- kernel 4: one sinkhorn column iteration ----------------------
__global__ void __launch_bounds__(256) sinkIterKernel(const int* __restrict__ gt,
                                                      int n, int src, int dst) {
    __shared__ float alpha[JJ];
    __shared__ float Cp[JJ];
    __shared__ float Bk[KCLS];
    int tid = threadIdx.x;
    if (tid < JJ) { alpha[tid] = 1.f / (8.f * gC[src][tid]); Cp[tid] = 0.f; }
    if (tid < KCLS) Bk[tid] = fmaxf(gBcnt[tid], 1.f);
    __syncthreads();

    int stride = gridDim.x * blockDim.x;
    for (int tok = blockIdx.x * blockDim.x + tid; tok < n; tok += stride) {
        int k = gt[tok];
        float4 a = *(const float4*)(gMasksOwn + (size_t)tok * 8);
        float4 b4 = *(const float4*)(gMasksOwn + (size_t)tok * 8 + 4);
        float e[8];
        e[0] = expf(a.x * INV_EPS);  e[1] = expf(a.y * INV_EPS);
        e[2] = expf(a.z * INV_EPS);  e[3] = expf(a.w * INV_EPS);
        e[4] = expf(b4.x * INV_EPS); e[5] = expf(b4.y * INV_EPS);
        e[6] = expf(b4.z * INV_EPS); e[7] = expf(b4.w * INV_EPS);
        float denom = 0.f;
#pragma unroll
        for (int mm = 0; mm < 8; mm++) denom += e[mm] * alpha[k * 8 + mm];
        float beta = 1.f / (Bk[k] * denom);
#pragma unroll
        for (int mm = 0; mm < 8; mm++) atomicAdd(&Cp[k * 8 + mm], e[mm] * beta);
    }
    __syncthreads();
    if (tid < JJ && Cp[tid] != 0.f) atomicAdd(&gC[dst][tid], Cp[tid]);
}

// ---------------- kernel 5: aggregation f += _c per (class,proto) bucket -------
// pass 0 handles classes {0,1}; pass 1 handles classes {2,3}
__global__ void __launch_bounds__(256) aggKernel(const float* __restrict__ X,
                                                 const int* __restrict__ gt,
                                                 const float* __restrict__ g,
                                                 const float* __restrict__ b,
                                                 int n, int pass) {
    __shared__ float fl[16 * DD];   // 32 KB
    __shared__ float lc[JJ];        // C3
    __shared__ float ncl[16];
    int tid = threadIdx.x;
    for (int i = tid; i < 16 * DD; i += 256) fl[i] = 0.f;
    if (tid < JJ) lc[tid] = gC[2][tid];
    if (tid < 16) ncl[tid] = 0.f;
    __syncthreads();

    int l = tid & 31, w = tid >> 5;
    int wid = blockIdx.x * 8 + w;
    int nw = gridDim.x * 8;

    for (int tok = wid; tok < n; tok += nw) {
        int bucket = -1;
        if (l == 0) {
            int k = gt[tok];
            if ((k >> 1) == pass && gPred[tok] == (unsigned char)k) {
                const float* mo = gMasksOwn + (size_t)tok * 8;
                float best = -1e30f; int bi = 0;
#pragma unroll
                for (int mm = 0; mm < 8; mm++) {
                    // argmax of E*alpha == argmax of s/eps - log(C3)
                    float v = mo[mm] * INV_EPS - __logf(lc[k * 8 + mm]);
                    if (v > best) { best = v; bi = mm; }
                }
                bucket = (k & 1) * 8 + bi;
                atomicAdd(&ncl[bucket], 1.f);
            }
        }
        bucket = __shfl_sync(0xffffffffu, bucket, 0);
        if (bucket >= 0) {
            float4 abc = gABC[tok];
            const float* x = X + (size_t)tok * DD;
            float* dst = fl + bucket * DD;
#pragma unroll
            for (int i = 0; i < 16; i++) {
                int d = l + 32 * i;
                float gv = g[d];
                float cd = abc.x * gv * x[d] + (abc.y * gv + abc.z * b[d]);
                atomicAdd(&dst[d], cd);   // bank == lane, conflict-free
            }
        }
    }
    __syncthreads();
    for (int i = tid; i < 16 * DD; i += 256) {
        float v = fl[i];
        if (v != 0.f) atomicAdd(&gF[pass * 16 * DD + i], v);
    }
    if (tid < 16) {
        float v = ncl[tid];
        if (v != 0.f) atomicAdd(&gNcnt[pass * 16 + tid], v);
    }
}

// ---------------- kernel 6: finalize new prototypes ----------------------------
__global__ void finalKernel(float* __restrict__ outp) {
    int tid = threadIdx.x;
    int w = tid >> 5, l = tid & 31;   // w = bucket j in [0,32)
    int k = w >> 3;

    float nj = gNcnt[w];
    float nsum = 0.f;
#pragma unroll
    for (int mm = 0; mm < 8; mm++) nsum += gNcnt[k * 8 + mm];
    bool valid = (nj != 0.f) && (gBcnt[k] > 0.f) && (nsum > 0.f);

    float v[16];
    float ss = 0.f;
#pragma unroll
    for (int i = 0; i < 16; i++) {
        v[i] = gF[w * DD + l + 32 * i];
        ss += v[i] * v[i];
    }
#pragma unroll
    for (int o = 16; o > 0; o >>= 1) ss += __shfl_xor_sync(0xffffffffu, ss, o);
    float inv = 1.f / fmaxf(sqrtf(ss), 1e-12f);

    float out[16];
    float ss2 = 0.f;
#pragma unroll
    for (int i = 0; i < 16; i++) {
        float fn = v[i] * inv;
        float base = gPN[w * DD + l + 32 * i];
        float r = valid ? (GAMMA_M * base + (1.f - GAMMA_M) * fn) : base;
        out[i] = r;
        ss2 += r * r;
    }
#pragma unroll
    for (int o = 16; o > 0; o >>= 1) ss2 += __shfl_xor_sync(0xffffffffu, ss2, o);
    float inv2 = 1.f / fmaxf(sqrtf(ss2), 1e-12f);
#pragma unroll
    for (int i = 0; i < 16; i++)
        outp[w * DD + l + 32 * i] = out[i] * inv2;
}

// ---------------- launch ---------------------------------------------------
extern "C" void kernel_launch(void* const* d_in, const int* in_sizes, int n_in,
                              void* d_out, int out_size) {
    const float* feats  = (const float*)d_in[0];
    const float* ln_g   = (const float*)d_in[1];
    const float* ln_b   = (const float*)d_in[2];
    const float* mg     = (const float*)d_in[3];
    const float* mb     = (const float*)d_in[4];
    const float* protos = (const float*)d_in[5];
    const int*   gt     = (const int*)d_in[6];

    int n = in_sizes[0] / DD;
    float* outseg = (float*)d_out;
    float* outp   = (float*)d_out + (size_t)(out_size - JJ * DD);

    initKernel<<<1, 1024>>>(protos, ln_g, ln_b);
    statsKernel<<<2048, 256>>>(feats, ln_g, ln_b, n);
    int gb = (n + 127) / 128;
    gemmKernel<<<gb, 256>>>(feats, gt, mg, mb, outseg, n);
    sinkIterKernel<<<512, 256>>>(gt, n, 0, 1);
    sinkIterKernel<<<512, 256>>>(gt, n, 1, 2);
    aggKernel<<<592, 256>>>(feats, gt, ln_g, ln_b, n, 0);
    aggKernel<<<592, 256>>>(feats, gt, ln_g, ln_b, n, 1);
    finalKernel<<<1, 1024>>>(outp);
}

// round 10
// speedup vs baseline: 1.3014x; 1.3014x over previous
#include <cuda_runtime.h>
#include <math.h>
#include <stdint.h>

#define NMAX 200704
#define DD 512
#define KCLS 4
#define MP 8
#define JJ 32           // KCLS*MP
#define INV_EPS 20.0f   // 1/0.05
#define GAMMA_M 0.999f

// ---------------- scratch (device globals; no allocations) ----------------
__device__ __align__(16) float gPN[JJ * DD];      // normalized prototypes [j][d]
__device__ __align__(16) float gWmat[DD * JJ];    // W[d][j] = g[d]*pN[j][d]
__device__ __align__(16) float gS1[JJ];
__device__ __align__(16) float gS2[JJ];
__device__ __align__(16) float gCst[4];           // Q0, R0, B2
__device__ __align__(16) float4 gABC[NMAX];       // (a, beta, c, 0) per token
__device__ __align__(16) float gE[NMAX * MP];     // E = exp(score/eps) own-class
__device__ unsigned char gPred[NMAX];
__device__ unsigned char gBucket[NMAX];           // 255 = not aggregated
__device__ __align__(16) float gC[3][JJ];         // sinkhorn column sums
__device__ __align__(16) float gBcnt[KCLS];
__device__ __align__(16) float gF[JJ * DD];
__device__ __align__(16) float gNcnt[JJ];

// ---------------- kernel 1: init -------------------------------------------
__global__ void initKernel(const float* __restrict__ protos,
                           const float* __restrict__ g,
                           const float* __restrict__ b) {
    int tid = threadIdx.x;
    int w = tid >> 5, l = tid & 31;

    for (int i = tid; i < JJ * DD; i += 1024) gF[i] = 0.f;
    if (tid < 3 * JJ) ((float*)gC)[tid] = 0.f;
    if (tid < JJ) gNcnt[tid] = 0.f;
    if (tid < KCLS) gBcnt[tid] = 0.f;

    {
        const float* p = protos + (size_t)w * DD;
        float v[16];
        float ss = 0.f;
#pragma unroll
        for (int i = 0; i < 16; i++) { v[i] = p[l + 32 * i]; ss += v[i] * v[i]; }
#pragma unroll
        for (int o = 16; o > 0; o >>= 1) ss += __shfl_xor_sync(0xffffffffu, ss, o);
        float inv = 1.f / fmaxf(sqrtf(ss), 1e-12f);
        float s1 = 0.f, s2 = 0.f;
#pragma unroll
        for (int i = 0; i < 16; i++) {
            int d = l + 32 * i;
            float pn = v[i] * inv;
            float gv = g[d], bv = b[d];
            gPN[w * DD + d] = pn;
            gWmat[d * JJ + w] = gv * pn;
            s1 += gv * pn;
            s2 += bv * pn;
        }
#pragma unroll
        for (int o = 16; o > 0; o >>= 1) {
            s1 += __shfl_xor_sync(0xffffffffu, s1, o);
            s2 += __shfl_xor_sync(0xffffffffu, s2, o);
        }
        if (l == 0) { gS1[w] = s1; gS2[w] = s2; }
    }

    if (w == 0) {
        float q0 = 0.f, r0 = 0.f, b2 = 0.f;
#pragma unroll
        for (int i = 0; i < 16; i++) {
            int d = l + 32 * i;
            float gv = g[d], bv = b[d];
            q0 += gv * gv; r0 += gv * bv; b2 += bv * bv;
        }
#pragma unroll
        for (int o = 16; o > 0; o >>= 1) {
            q0 += __shfl_xor_sync(0xffffffffu, q0, o);
            r0 += __shfl_xor_sync(0xffffffffu, r0, o);
            b2 += __shfl_xor_sync(0xffffffffu, b2, o);
        }
        if (l == 0) { gCst[0] = q0; gCst[1] = r0; gCst[2] = b2; gCst[3] = 0.f; }
    }
}

// ---------------- kernel 2: per-token LN/L2 stats ---------------------------
__global__ void __launch_bounds__(256) statsKernel(const float* __restrict__ X,
                                                   const float* __restrict__ g,
                                                   const float* __restrict__ b,
                                                   int n) {
    int l = threadIdx.x & 31;
    int wid = (blockIdx.x * blockDim.x + threadIdx.x) >> 5;
    int nw = (gridDim.x * blockDim.x) >> 5;
    float Q0 = gCst[0], R0 = gCst[1], B2 = gCst[2];

    // cache g^2 and g*b for this lane's 16 dims (4 float4)
    float gg[16], gb[16];
#pragma unroll
    for (int i = 0; i < 4; i++) {
        int d4 = (l + 32 * i) * 4;
        float4 g4 = *(const float4*)(g + d4);
        float4 b4 = *(const float4*)(b + d4);
        gg[i * 4 + 0] = g4.x * g4.x; gb[i * 4 + 0] = g4.x * b4.x;
        gg[i * 4 + 1] = g4.y * g4.y; gb[i * 4 + 1] = g4.y * b4.y;
        gg[i * 4 + 2] = g4.z * g4.z; gb[i * 4 + 2] = g4.z * b4.z;
        gg[i * 4 + 3] = g4.w * g4.w; gb[i * 4 + 3] = g4.w * b4.w;
    }

    for (int tok = wid; tok < n; tok += nw) {
        const float* x = X + (size_t)tok * DD;
        float sx = 0.f, sxx = 0.f, q2 = 0.f, q1 = 0.f, r1 = 0.f;
#pragma unroll
        for (int i = 0; i < 4; i++) {
            float4 xv = *(const float4*)(x + (l + 32 * i) * 4);
            float xs[4] = {xv.x, xv.y, xv.z, xv.w};
#pragma unroll
            for (int u = 0; u < 4; u++) {
                float v = xs[u];
                float v2 = v * v;
                sx += v; sxx += v2;
                q2 += v2 * gg[i * 4 + u];
                q1 += v * gg[i * 4 + u];
                r1 += v * gb[i * 4 + u];
            }
        }
#pragma unroll
        for (int o = 16; o > 0; o >>= 1) {
            sx  += __shfl_xor_sync(0xffffffffu, sx,  o);
            sxx += __shfl_xor_sync(0xffffffffu, sxx, o);
            q2  += __shfl_xor_sync(0xffffffffu, q2,  o);
            q1  += __shfl_xor_sync(0xffffffffu, q1,  o);
            r1  += __shfl_xor_sync(0xffffffffu, r1,  o);
        }
        if (l == 0) {
            const float invD = 1.f / 512.f;
            float mu = sx * invD;
            float var = sxx * invD - mu * mu;
            float istd = rsqrtf(var + 1e-5f);
            float ysq = istd * istd * (q2 - 2.f * mu * q1 + mu * mu * Q0)
                      + 2.f * istd * (r1 - mu * R0) + B2;
            float yn = fmaxf(sqrtf(fmaxf(ysq, 0.f)), 1e-12f);
            float inv = 1.f / yn;
            gABC[tok] = make_float4(istd * inv, -istd * mu * inv, inv, 0.f);
        }
    }
}

// ---------------- kernel 3: GEMM [256tok x 32proto] + fused epilogue --------
__global__ void __launch_bounds__(256) gemmKernel(const float* __restrict__ X,
                                                  const int* __restrict__ gt,
                                                  const float* __restrict__ mg,
                                                  const float* __restrict__ mb,
                                                  float* __restrict__ outseg,
                                                  int n) {
    __shared__ float Xs[256 * 36];   // 36 KB; reused as masks tile
    __shared__ float Ws[32 * 36];
    __shared__ float S1s[JJ], S2s[JJ];
    __shared__ float Cp[8][JJ];      // per-warp sinkhorn col partials
    __shared__ float Bp[KCLS];

    int tid = threadIdx.x;
    int wrp = tid >> 5;
    int jg = tid & 7;        // proto group (4 protos)
    int tg = tid >> 3;       // token group (8 tokens)
    int tokBase = blockIdx.x * 256;

    if (tid < JJ) { S1s[tid] = gS1[tid]; S2s[tid] = gS2[tid]; }
    if (tid < 8 * JJ) ((float*)Cp)[tid] = 0.f;
    if (tid < KCLS) Bp[tid] = 0.f;

    float acc[8][4] = {};

    for (int kc = 0; kc < 512; kc += 32) {
        // stage X chunk [256][32]
#pragma unroll
        for (int r = 0; r < 8; r++) {
            int li = tid + 256 * r;
            int row = li >> 3;
            int c4 = (li & 7) * 4;
            int tok = tokBase + row;
            float4 v = (tok < n)
                ? *(const float4*)(X + (size_t)tok * 512 + kc + c4)
                : make_float4(0.f, 0.f, 0.f, 0.f);
            *(float4*)(Xs + row * 36 + c4) = v;
        }
        // stage W chunk [32][32]
        {
            int row = tid >> 3;
            int c4 = (tid & 7) * 4;
            *(float4*)(Ws + row * 36 + c4) =
                *(const float4*)(gWmat + (size_t)(kc + row) * 32 + c4);
        }
        __syncthreads();
#pragma unroll
        for (int kq = 0; kq < 8; kq++) {
            int q = (kq + tg) & 7;           // rotation de-conflicts Xs banks
            const float* wb = Ws + q * 4 * 36 + jg * 4;
            float4 w0 = *(const float4*)(wb);
            float4 w1 = *(const float4*)(wb + 36);
            float4 w2 = *(const float4*)(wb + 72);
            float4 w3 = *(const float4*)(wb + 108);
#pragma unroll
            for (int i = 0; i < 8; i++) {
                float4 xq = *(const float4*)(Xs + (tg * 8 + i) * 36 + q * 4);
                acc[i][0] = fmaf(xq.x, w0.x, acc[i][0]);
                acc[i][1] = fmaf(xq.x, w0.y, acc[i][1]);
                acc[i][2] = fmaf(xq.x, w0.z, acc[i][2]);
                acc[i][3] = fmaf(xq.x, w0.w, acc[i][3]);
                acc[i][0] = fmaf(xq.y, w1.x, acc[i][0]);
                acc[i][1] = fmaf(xq.y, w1.y, acc[i][1]);
                acc[i][2] = fmaf(xq.y, w1.z, acc[i][2]);
                acc[i][3] = fmaf(xq.y, w1.w, acc[i][3]);
                acc[i][0] = fmaf(xq.z, w2.x, acc[i][0]);
                acc[i][1] = fmaf(xq.z, w2.y, acc[i][1]);
                acc[i][2] = fmaf(xq.z, w2.z, acc[i][2]);
                acc[i][3] = fmaf(xq.z, w2.w, acc[i][3]);
                acc[i][0] = fmaf(xq.w, w3.x, acc[i][0]);
                acc[i][1] = fmaf(xq.w, w3.y, acc[i][1]);
                acc[i][2] = fmaf(xq.w, w3.z, acc[i][2]);
                acc[i][3] = fmaf(xq.w, w3.w, acc[i][3]);
            }
        }
        __syncthreads();
    }

    // dump accumulators to smem masks tile (reuse Xs)
#pragma unroll
    for (int i = 0; i < 8; i++)
        *(float4*)(Xs + (tg * 8 + i) * 36 + jg * 4) =
            make_float4(acc[i][0], acc[i][1], acc[i][2], acc[i][3]);
    __syncthreads();

    // epilogue: one thread per token
    int tok = tokBase + tid;
    if (tok < n) {
        float4 abc = gABC[tok];
        float m[32];
        float mx[4];
#pragma unroll
        for (int k = 0; k < 4; k++) {
            float best = -1e30f;
#pragma unroll
            for (int mm = 0; mm < 8; mm++) {
                int j = k * 8 + mm;
                float v = abc.x * Xs[tid * 36 + j] + abc.y * S1s[j] + abc.z * S2s[j];
                m[j] = v;
                best = fmaxf(best, v);
            }
            mx[k] = best;
        }
        float mu = 0.25f * (mx[0] + mx[1] + mx[2] + mx[3]);
        float var = 0.f;
#pragma unroll
        for (int k = 0; k < 4; k++) { float d = mx[k] - mu; var += d * d; }
        var *= 0.25f;
        float is4 = 1.f / sqrtf(var + 1e-5f);
        float o[4];
        int pred = 0; float bo = -1e30f;
#pragma unroll
        for (int k = 0; k < 4; k++) {
            o[k] = (mx[k] - mu) * is4 * mg[k] + mb[k];
            if (o[k] > bo) { bo = o[k]; pred = k; }
        }
        *(float4*)(outseg + (size_t)tok * 4) = make_float4(o[0], o[1], o[2], o[3]);
        gPred[tok] = (unsigned char)pred;

        int kk = gt[tok];
        float e[8];
#pragma unroll
        for (int mm = 0; mm < 8; mm++) e[mm] = expf(m[kk * 8 + mm] * INV_EPS);
        *(float4*)(gE + (size_t)tok * 8)     = make_float4(e[0], e[1], e[2], e[3]);
        *(float4*)(gE + (size_t)tok * 8 + 4) = make_float4(e[4], e[5], e[6], e[7]);
#pragma unroll
        for (int mm = 0; mm < 8; mm++)
            atomicAdd(&Cp[wrp][kk * 8 + mm], e[mm]);
        atomicAdd(&Bp[kk], 1.f);
    }
    __syncthreads();
    if (tid < JJ) {
        float s = 0.f;
#pragma unroll
        for (int w = 0; w < 8; w++) s += Cp[w][tid];
        if (s != 0.f) atomicAdd(&gC[0][tid], s);
    }
    if (tid < KCLS && Bp[tid] != 0.f) atomicAdd(&gBcnt[tid], Bp[tid]);
}

// ---------------- kernel 4: one sinkhorn column iteration -------------------
__global__ void __launch_bounds__(256) sinkIterKernel(const int* __restrict__ gt,
                                                      int n, int src, int dst) {
    __shared__ float alpha[JJ];
    __shared__ float Cp[8][JJ];
    __shared__ float Bk[KCLS];
    int tid = threadIdx.x;
    int wrp = tid >> 5;
    if (tid < JJ) alpha[tid] = 1.f / (8.f * gC[src][tid]);
    if (tid < 8 * JJ) ((float*)Cp)[tid] = 0.f;
    if (tid < KCLS) Bk[tid] = fmaxf(gBcnt[tid], 1.f);
    __syncthreads();

    int stride = gridDim.x * blockDim.x;
    for (int tok = blockIdx.x * blockDim.x + tid; tok < n; tok += stride) {
        int k = gt[tok];
        float4 a = *(const float4*)(gE + (size_t)tok * 8);
        float4 b4 = *(const float4*)(gE + (size_t)tok * 8 + 4);
        float e[8] = {a.x, a.y, a.z, a.w, b4.x, b4.y, b4.z, b4.w};
        float denom = 0.f;
#pragma unroll
        for (int mm = 0; mm < 8; mm++) denom += e[mm] * alpha[k * 8 + mm];
        float beta = 1.f / (Bk[k] * denom);
#pragma unroll
        for (int mm = 0; mm < 8; mm++) atomicAdd(&Cp[wrp][k * 8 + mm], e[mm] * beta);
    }
    __syncthreads();
    if (tid < JJ) {
        float s = 0.f;
#pragma unroll
        for (int w = 0; w < 8; w++) s += Cp[w][tid];
        if (s != 0.f) atomicAdd(&gC[dst][tid], s);
    }
}

// ---------------- kernel 5: bucket assignment -------------------------------
__global__ void __launch_bounds__(256) bucketKernel(const int* __restrict__ gt, int n) {
    __shared__ float invc[JJ];
    int tid = threadIdx.x;
    if (tid < JJ) invc[tid] = 1.f / gC[2][tid];
    __syncthreads();
    int stride = gridDim.x * blockDim.x;
    for (int tok = blockIdx.x * blockDim.x + tid; tok < n; tok += stride) {
        int k = gt[tok];
        unsigned char bkt = 255;
        if (gPred[tok] == (unsigned char)k) {
            float4 a = *(const float4*)(gE + (size_t)tok * 8);
            float4 b4 = *(const float4*)(gE + (size_t)tok * 8 + 4);
            float e[8] = {a.x, a.y, a.z, a.w, b4.x, b4.y, b4.z, b4.w};
            float best = -1e30f; int bi = 0;
#pragma unroll
            for (int mm = 0; mm < 8; mm++) {
                float v = e[mm] * invc[k * 8 + mm];
                if (v > best) { best = v; bi = mm; }
            }
            bkt = (unsigned char)(k * 8 + bi);
        }
        gBucket[tok] = bkt;
    }
}

// ---------------- kernel 6: aggregation (register accumulators) -------------
#define AGG_SLICES 44
__global__ void __launch_bounds__(256) aggKernel(const float* __restrict__ X,
                                                 const float* __restrict__ g,
                                                 const float* __restrict__ b,
                                                 int n) {
    int l = threadIdx.x & 31;
    int wgid = blockIdx.x * 8 + (threadIdx.x >> 5);
    int bucket = wgid & 31;
    int slice = wgid >> 5;               // 0..AGG_SLICES-1
    if (slice >= AGG_SLICES) return;

    int chunk = (n + AGG_SLICES - 1) / AGG_SLICES;
    int start = slice * chunk;
    int end = min(start + chunk, n);

    float gl[16], bl[16], acc[16];
#pragma unroll
    for (int i = 0; i < 16; i++) {
        gl[i] = g[l + 32 * i];
        bl[i] = b[l + 32 * i];
        acc[i] = 0.f;
    }
    int cnt = 0;

    for (int t0 = start; t0 < end; t0 += 32) {
        int tok = t0 + l;
        int myb = (tok < end) ? (int)gBucket[tok] : -1;
        unsigned mask = __ballot_sync(0xffffffffu, myb == bucket);
        cnt += __popc(mask);
        while (mask) {
            int bit = __ffs(mask) - 1;
            mask &= mask - 1;
            int th = t0 + bit;
            float4 abc = gABC[th];
            const float* x = X + (size_t)th * DD;
#pragma unroll
            for (int i = 0; i < 16; i++) {
                float cd = fmaf(abc.x * gl[i], x[l + 32 * i],
                                fmaf(abc.y, gl[i], abc.z * bl[i]));
                acc[i] += cd;
            }
        }
    }
#pragma unroll
    for (int i = 0; i < 16; i++)
        if (acc[i] != 0.f) atomicAdd(&gF[bucket * DD + l + 32 * i], acc[i]);
    if (l == 0 && cnt > 0) atomicAdd(&gNcnt[bucket], (float)cnt);
}

// ---------------- kernel 7: finalize new prototypes --------------------------
__global__ void finalKernel(float* __restrict__ outp) {
    int tid = threadIdx.x;
    int w = tid >> 5, l = tid & 31;   // w = bucket j
    int k = w >> 3;

    float nj = gNcnt[w];
    float nsum = 0.f;
#pragma unroll
    for (int mm = 0; mm < 8; mm++) nsum += gNcnt[k * 8 + mm];
    bool valid = (nj != 0.f) && (gBcnt[k] > 0.f) && (nsum > 0.f);

    float v[16];
    float ss = 0.f;
#pragma unroll
    for (int i = 0; i < 16; i++) {
        v[i] = gF[w * DD + l + 32 * i];
        ss += v[i] * v[i];
    }
#pragma unroll
    for (int o = 16; o > 0; o >>= 1) ss += __shfl_xor_sync(0xffffffffu, ss, o);
    float inv = 1.f / fmaxf(sqrtf(ss), 1e-12f);

    float out[16];
    float ss2 = 0.f;
#pragma unroll
    for (int i = 0; i < 16; i++) {
        float fn = v[i] * inv;
        float base = gPN[w * DD + l + 32 * i];
        float r = valid ? (GAMMA_M * base + (1.f - GAMMA_M) * fn) : base;
        out[i] = r;
        ss2 += r * r;
    }
#pragma unroll
    for (int o = 16; o > 0; o >>= 1) ss2 += __shfl_xor_sync(0xffffffffu, ss2, o);
    float inv2 = 1.f / fmaxf(sqrtf(ss2), 1e-12f);
#pragma unroll
    for (int i = 0; i < 16; i++)
        outp[w * DD + l + 32 * i] = out[i] * inv2;
}

// ---------------- launch ---------------------------------------------------
extern "C" void kernel_launch(void* const* d_in, const int* in_sizes, int n_in,
                              void* d_out, int out_size) {
    const float* feats  = (const float*)d_in[0];
    const float* ln_g   = (const float*)d_in[1];
    const float* ln_b   = (const float*)d_in[2];
    const float* mg     = (const float*)d_in[3];
    const float* mb     = (const float*)d_in[4];
    const float* protos = (const float*)d_in[5];
    const int*   gt     = (const int*)d_in[6];

    int n = in_sizes[0] / DD;
    float* outseg = (float*)d_out;
    float* outp   = (float*)d_out + (size_t)(out_size - JJ * DD);

    initKernel<<<1, 1024>>>(protos, ln_g, ln_b);
    statsKernel<<<2048, 256>>>(feats, ln_g, ln_b, n);
    gemmKernel<<<(n + 255) / 256, 256>>>(feats, gt, mg, mb, outseg, n);
    sinkIterKernel<<<512, 256>>>(gt, n, 0, 1);
    sinkIterKernel<<<512, 256>>>(gt, n, 1, 2);
    bucketKernel<<<512, 256>>>(gt, n);
    aggKernel<<<(32 * AGG_SLICES + 7) / 8, 256>>>(feats, ln_g, ln_b, n);
    finalKernel<<<1, 1024>>>(outp);
}

// round 12
// speedup vs baseline: 1.5461x; 1.1881x over previous
#include <cuda_runtime.h>
#include <cuda_bf16.h>
#include <math.h>
#include <stdint.h>

#define DD 512
#define KCLS 4
#define MP 8
#define JJ 32
#define INV_EPS 20.0f
#define GAMMA_M 0.999f
#define NMAX 200704
#define BROW 260            // u32 row stride for W images (pad: 260 % 32 = 4 -> conflict-free)

// ---------------- device scratch (no allocations) ---------------------------
__device__ __align__(16) float gPN[JJ * DD];
__device__ __align__(16) float gS1[JJ];
__device__ __align__(16) float gS2[JJ];
__device__ __align__(16) float gCst[4];                 // Q0, R0, B2
__device__ __align__(16) float4 gGGB[DD / 2];           // (gg0,gg1,gb0,gb1) per k-pair
__device__ __align__(16) uint32_t gW2[2 * JJ * BROW];   // bf16x2 W images: hi then lo
__device__ __align__(16) float4 gABC[NMAX];
__device__ __align__(16) float gE[NMAX * MP];
__device__ unsigned char gPred[NMAX];
__device__ unsigned char gBucket[NMAX];
__device__ __align__(16) float gC[3][JJ];
__device__ __align__(16) float gBcnt[KCLS];
__device__ __align__(16) float gF[JJ * DD];
__device__ __align__(16) float gNcnt[JJ];

// ---------------- helpers ----------------------------------------------------
__device__ __forceinline__ uint32_t packbf(float lo, float hi) {
    uint32_t r;
    asm("cvt.rn.bf16x2.f32 %0, %1, %2;" : "=r"(r) : "f"(hi), "f"(lo));
    return r;
}
__device__ __forceinline__ float2 residbf(float2 v, uint32_t h) {
    __nv_bfloat162 hb = *reinterpret_cast<__nv_bfloat162*>(&h);
    return make_float2(v.x - __bfloat162float(hb.x), v.y - __bfloat162float(hb.y));
}
__device__ __forceinline__ void mma_bf16(float* c, uint32_t a0, uint32_t a1,
                                         uint32_t a2, uint32_t a3,
                                         uint32_t b0, uint32_t b1) {
    asm volatile(
        "mma.sync.aligned.m16n8k16.row.col.f32.bf16.bf16.f32 "
        "{%0,%1,%2,%3}, {%4,%5,%6,%7}, {%8,%9}, {%0,%1,%2,%3};"
        : "+f"(c[0]), "+f"(c[1]), "+f"(c[2]), "+f"(c[3])
        : "r"(a0), "r"(a1), "r"(a2), "r"(a3), "r"(b0), "r"(b1));
}
__device__ __forceinline__ void stat2(float2 v, float gg0, float gg1,
                                      float gb0, float gb1,
                                      float& sx, float& sxx, float& q2,
                                      float& q1, float& r1) {
    float x2;
    x2 = v.x * v.x; sx += v.x; sxx += x2;
    q2 = fmaf(x2, gg0, q2); q1 = fmaf(v.x, gg0, q1); r1 = fmaf(v.x, gb0, r1);
    x2 = v.y * v.y; sx += v.y; sxx += x2;
    q2 = fmaf(x2, gg1, q2); q1 = fmaf(v.y, gg1, q1); r1 = fmaf(v.y, gb1, r1);
}

// ---------------- kernel 1: init ---------------------------------------------
__global__ void initKernel(const float* __restrict__ protos,
                           const float* __restrict__ g,
                           const float* __restrict__ b) {
    int tid = threadIdx.x;
    int w = tid >> 5, l = tid & 31;     // warp w handles prototype j = w

    for (int i = tid; i < JJ * DD; i += 1024) gF[i] = 0.f;
    if (tid < 3 * JJ) ((float*)gC)[tid] = 0.f;
    if (tid < JJ) gNcnt[tid] = 0.f;
    if (tid < KCLS) gBcnt[tid] = 0.f;
    if (tid < DD / 2) {
        int d = tid * 2;
        float g0 = g[d], g1 = g[d + 1];
        gGGB[tid] = make_float4(g0 * g0, g1 * g1, g0 * b[d], g1 * b[d + 1]);
    }

    {   // prototype j = w: normalize, build W bf16 hi/lo pair images
        const float* p = protos + (size_t)w * DD;
        float v[16];
        float ss = 0.f;
#pragma unroll
        for (int i = 0; i < 8; i++) {
            int pr = l + 32 * i;             // pair index
            v[2 * i]     = p[2 * pr];
            v[2 * i + 1] = p[2 * pr + 1];
            ss += v[2 * i] * v[2 * i] + v[2 * i + 1] * v[2 * i + 1];
        }
#pragma unroll
        for (int o = 16; o > 0; o >>= 1) ss += __shfl_xor_sync(0xffffffffu, ss, o);
        float inv = 1.f / fmaxf(sqrtf(ss), 1e-12f);
        float s1 = 0.f, s2 = 0.f;
#pragma unroll
        for (int i = 0; i < 8; i++) {
            int pr = l + 32 * i;
            int d0 = 2 * pr, d1 = d0 + 1;
            float pn0 = v[2 * i] * inv, pn1 = v[2 * i + 1] * inv;
            gPN[w * DD + d0] = pn0;
            gPN[w * DD + d1] = pn1;
            float g0 = g[d0], g1 = g[d1];
            s1 += g0 * pn0 + g1 * pn1;
            s2 += b[d0] * pn0 + b[d1] * pn1;
            float w0 = g0 * pn0, w1 = g1 * pn1;
            uint32_t hi = packbf(w0, w1);
            float2 rs = residbf(make_float2(w0, w1), hi);
            uint32_t lo = packbf(rs.x, rs.y);
            gW2[w * BROW + pr] = hi;
            gW2[JJ * BROW + w * BROW + pr] = lo;
        }
#pragma unroll
        for (int o = 16; o > 0; o >>= 1) {
            s1 += __shfl_xor_sync(0xffffffffu, s1, o);
            s2 += __shfl_xor_sync(0xffffffffu, s2, o);
        }
        if (l == 0) { gS1[w] = s1; gS2[w] = s2; }
    }

    if (w == 0) {
        float q0 = 0.f, r0 = 0.f, b2 = 0.f;
#pragma unroll
        for (int i = 0; i < 16; i++) {
            int d = l + 32 * i;
            float gv = g[d], bv = b[d];
            q0 += gv * gv; r0 += gv * bv; b2 += bv * bv;
        }
#pragma unroll
        for (int o = 16; o > 0; o >>= 1) {
            q0 += __shfl_xor_sync(0xffffffffu, q0, o);
            r0 += __shfl_xor_sync(0xffffffffu, r0, o);
            b2 += __shfl_xor_sync(0xffffffffu, b2, o);
        }
        if (l == 0) { gCst[0] = q0; gCst[1] = r0; gCst[2] = b2; gCst[3] = 0.f; }
    }
}

// ---------------- kernel 2: fused stats + bf16-split mma GEMM + epilogue ------
// dynamic smem: W hi/lo images 2*32*260*4 = 66560 B; overlaid later by masks[128][36]
#define DSM_BYTES (2 * JJ * BROW * 4)

__global__ void __launch_bounds__(256) fusedKernel(const float* __restrict__ X,
                                                   const int* __restrict__ gt,
                                                   const float* __restrict__ mg,
                                                   const float* __restrict__ mb,
                                                   float* __restrict__ outseg,
                                                   int n) {
    extern __shared__ char dsm[];
    uint32_t* BsmHi = (uint32_t*)dsm;
    uint32_t* BsmLo = BsmHi + JJ * BROW;
    float* Msm = (float*)dsm;                 // overlay after mma loop
    __shared__ float4 sGGB[DD / 2];
    __shared__ float4 sABS[128];
    __shared__ float sS1[JJ], sS2[JJ];
    __shared__ float sCp[4][JJ];
    __shared__ float sBp[KCLS];

    int tid = threadIdx.x;
    int w = tid >> 5, lane = tid & 31;
    int q = lane & 3, rq = lane >> 2;
    int tokBase = blockIdx.x * 128;

    {   // stage W images (4160 uint4)
        const uint4* src = (const uint4*)gW2;
        uint4* dst = (uint4*)dsm;
        for (int i = tid; i < (2 * JJ * BROW) / 4; i += 256) dst[i] = src[i];
    }
    for (int i = tid; i < DD / 2; i += 256) sGGB[i] = gGGB[i];
    if (tid < JJ) { sS1[tid] = gS1[tid]; sS2[tid] = gS2[tid]; }
    if (tid < 4 * JJ) ((float*)sCp)[tid] = 0.f;
    if (tid < KCLS) sBp[tid] = 0.f;
    __syncthreads();

    int r0 = tokBase + w * 16 + rq;       // this thread's two A rows
    int r1 = r0 + 8;
    const float* x0 = X + (size_t)(r0 < n ? r0 : 0) * DD;
    const float* x1 = X + (size_t)(r1 < n ? r1 : 0) * DD;

    float acc[4][4] = {};
    float sxA = 0.f, sxxA = 0.f, q2A = 0.f, q1A = 0.f, r1A = 0.f;
    float sxB = 0.f, sxxB = 0.f, q2B = 0.f, q1B = 0.f, r1B = 0.f;

    const uint32_t* bRowHi = BsmHi + rq * BROW;   // B fragment row n = lane>>2 (per ntile +8*BROW)
    const uint32_t* bRowLo = BsmLo + rq * BROW;

#pragma unroll 4
    for (int kb = 0; kb < DD; kb += 16) {
        int kp = (kb >> 1) + q;
        float2 xa0 = *(const float2*)(x0 + kb + 2 * q);
        float2 xa2 = *(const float2*)(x0 + kb + 2 * q + 8);
        float2 xb0 = *(const float2*)(x1 + kb + 2 * q);
        float2 xb2 = *(const float2*)(x1 + kb + 2 * q + 8);
        float4 gq0 = sGGB[kp];
        float4 gq2 = sGGB[kp + 4];

        stat2(xa0, gq0.x, gq0.y, gq0.z, gq0.w, sxA, sxxA, q2A, q1A, r1A);
        stat2(xa2, gq2.x, gq2.y, gq2.z, gq2.w, sxA, sxxA, q2A, q1A, r1A);
        stat2(xb0, gq0.x, gq0.y, gq0.z, gq0.w, sxB, sxxB, q2B, q1B, r1B);
        stat2(xb2, gq2.x, gq2.y, gq2.z, gq2.w, sxB, sxxB, q2B, q1B, r1B);

        uint32_t a0h = packbf(xa0.x, xa0.y);
        uint32_t a1h = packbf(xb0.x, xb0.y);
        uint32_t a2h = packbf(xa2.x, xa2.y);
        uint32_t a3h = packbf(xb2.x, xb2.y);
        float2 rr;
        rr = residbf(xa0, a0h); uint32_t a0l = packbf(rr.x, rr.y);
        rr = residbf(xb0, a1h); uint32_t a1l = packbf(rr.x, rr.y);
        rr = residbf(xa2, a2h); uint32_t a2l = packbf(rr.x, rr.y);
        rr = residbf(xb2, a3h); uint32_t a3l = packbf(rr.x, rr.y);

#pragma unroll
        for (int nt = 0; nt < 4; nt++) {
            uint32_t bh0 = bRowHi[nt * 8 * BROW + kp];
            uint32_t bh1 = bRowHi[nt * 8 * BROW + kp + 4];
            uint32_t bl0 = bRowLo[nt * 8 * BROW + kp];
            uint32_t bl1 = bRowLo[nt * 8 * BROW + kp + 4];
            mma_bf16(acc[nt], a0h, a1h, a2h, a3h, bh0, bh1);
            mma_bf16(acc[nt], a0h, a1h, a2h, a3h, bl0, bl1);
            mma_bf16(acc[nt], a0l, a1l, a2l, a3l, bh0, bh1);
        }
    }

    // quad-reduce stats (lanes differing in bits 0,1 share the same rows)
#pragma unroll
    for (int o = 1; o <= 2; o <<= 1) {
        sxA  += __shfl_xor_sync(0xffffffffu, sxA,  o);
        sxxA += __shfl_xor_sync(0xffffffffu, sxxA, o);
        q2A  += __shfl_xor_sync(0xffffffffu, q2A,  o);
        q1A  += __shfl_xor_sync(0xffffffffu, q1A,  o);
        r1A  += __shfl_xor_sync(0xffffffffu, r1A,  o);
        sxB  += __shfl_xor_sync(0xffffffffu, sxB,  o);
        sxxB += __shfl_xor_sync(0xffffffffu, sxxB, o);
        q2B  += __shfl_xor_sync(0xffffffffu, q2B,  o);
        q1B  += __shfl_xor_sync(0xffffffffu, q1B,  o);
        r1B  += __shfl_xor_sync(0xffffffffu, r1B,  o);
    }
    if (q == 0) {
        float Q0 = gCst[0], R0 = gCst[1], B2 = gCst[2];
        const float invD = 1.f / 512.f;
        {
            float mu = sxA * invD;
            float var = sxxA * invD - mu * mu;
            float istd = rsqrtf(var + 1e-5f);
            float ysq = istd * istd * (q2A - 2.f * mu * q1A + mu * mu * Q0)
                      + 2.f * istd * (r1A - mu * R0) + B2;
            float inv = 1.f / fmaxf(sqrtf(fmaxf(ysq, 0.f)), 1e-12f);
            float4 abc = make_float4(istd * inv, -istd * mu * inv, inv, 0.f);
            sABS[w * 16 + rq] = abc;
            if (r0 < n) gABC[r0] = abc;
        }
        {
            float mu = sxB * invD;
            float var = sxxB * invD - mu * mu;
            float istd = rsqrtf(var + 1e-5f);
            float ysq = istd * istd * (q2B - 2.f * mu * q1B + mu * mu * Q0)
                      + 2.f * istd * (r1B - mu * R0) + B2;
            float inv = 1.f / fmaxf(sqrtf(fmaxf(ysq, 0.f)), 1e-12f);
            float4 abc = make_float4(istd * inv, -istd * mu * inv, inv, 0.f);
            sABS[w * 16 + rq + 8] = abc;
            if (r1 < n) gABC[r1] = abc;
        }
    }

    __syncthreads();   // everyone done reading B -> overlay masks
    {
        int rl = w * 16 + rq;
        int cb = q * 2;
#pragma unroll
        for (int nt = 0; nt < 4; nt++) {
            Msm[rl * 36 + nt * 8 + cb]           = acc[nt][0];
            Msm[rl * 36 + nt * 8 + cb + 1]       = acc[nt][1];
            Msm[(rl + 8) * 36 + nt * 8 + cb]     = acc[nt][2];
            Msm[(rl + 8) * 36 + nt * 8 + cb + 1] = acc[nt][3];
        }
    }
    __syncthreads();

    // epilogue: one thread per token (threads 0..127)
    if (tid < 128) {
        int tok = tokBase + tid;
        if (tok < n) {
            float4 abc = sABS[tid];
            float m[32];
            float mx[4];
#pragma unroll
            for (int k = 0; k < 4; k++) {
                float best = -1e30f;
#pragma unroll
                for (int mm = 0; mm < 8; mm++) {
                    int j = k * 8 + mm;
                    float v = abc.x * Msm[tid * 36 + j] + abc.y * sS1[j] + abc.z * sS2[j];
                    m[j] = v;
                    best = fmaxf(best, v);
                }
                mx[k] = best;
            }
            float mu = 0.25f * (mx[0] + mx[1] + mx[2] + mx[3]);
            float var = 0.f;
#pragma unroll
            for (int k = 0; k < 4; k++) { float d = mx[k] - mu; var += d * d; }
            var *= 0.25f;
            float is4 = 1.f / sqrtf(var + 1e-5f);
            float o[4];
            int pred = 0; float bo = -1e30f;
#pragma unroll
            for (int k = 0; k < 4; k++) {
                o[k] = (mx[k] - mu) * is4 * mg[k] + mb[k];
                if (o[k] > bo) { bo = o[k]; pred = k; }
            }
            *(float4*)(outseg + (size_t)tok * 4) = make_float4(o[0], o[1], o[2], o[3]);
            gPred[tok] = (unsigned char)pred;

            int kk = gt[tok];
            float e[8];
#pragma unroll
            for (int mm = 0; mm < 8; mm++) e[mm] = expf(m[kk * 8 + mm] * INV_EPS);
            *(float4*)(gE + (size_t)tok * 8)     = make_float4(e[0], e[1], e[2], e[3]);
            *(float4*)(gE + (size_t)tok * 8 + 4) = make_float4(e[4], e[5], e[6], e[7]);
#pragma unroll
            for (int mm = 0; mm < 8; mm++)
                atomicAdd(&sCp[tid >> 5][kk * 8 + mm], e[mm]);
            atomicAdd(&sBp[kk], 1.f);
        }
    }
    __syncthreads();
    if (tid < JJ) {
        float s = sCp[0][tid] + sCp[1][tid] + sCp[2][tid] + sCp[3][tid];
        if (s != 0.f) atomicAdd(&gC[0][tid], s);
    }
    if (tid < KCLS && sBp[tid] != 0.f) atomicAdd(&gBcnt[tid], sBp[tid]);
}

// ---------------- kernel 3: one sinkhorn column iteration --------------------
__global__ void __launch_bounds__(512) sinkIterKernel(const int* __restrict__ gt,
                                                      int n, int src, int dst) {
    __shared__ float alpha[JJ];
    __shared__ float Cp[16][JJ];
    __shared__ float Bk[KCLS];
    int tid = threadIdx.x;
    int wrp = tid >> 5;
    if (tid < JJ) alpha[tid] = 1.f / fmaxf(8.f * gC[src][tid], 1e-30f);
    if (tid < 16 * JJ) ((float*)Cp)[tid] = 0.f;
    if (tid < KCLS) Bk[tid] = fmaxf(gBcnt[tid], 1.f);
    __syncthreads();

    int stride = gridDim.x * blockDim.x;
    for (int tok = blockIdx.x * blockDim.x + tid; tok < n; tok += stride) {
        int k = gt[tok];
        float4 a = *(const float4*)(gE + (size_t)tok * 8);
        float4 b4 = *(const float4*)(gE + (size_t)tok * 8 + 4);
        float e[8] = {a.x, a.y, a.z, a.w, b4.x, b4.y, b4.z, b4.w};
        float denom = 0.f;
#pragma unroll
        for (int mm = 0; mm < 8; mm++) denom += e[mm] * alpha[k * 8 + mm];
        float beta = 1.f / fmaxf(Bk[k] * denom, 1e-30f);
#pragma unroll
        for (int mm = 0; mm < 8; mm++) atomicAdd(&Cp[wrp][k * 8 + mm], e[mm] * beta);
    }
    __syncthreads();
    if (tid < JJ) {
        float s = 0.f;
#pragma unroll
        for (int w = 0; w < 16; w++) s += Cp[w][tid];
        if (s != 0.f) atomicAdd(&gC[dst][tid], s);
    }
}

// ---------------- kernel 4: bucket assignment --------------------------------
__global__ void __launch_bounds__(256) bucketKernel(const int* __restrict__ gt, int n) {
    __shared__ float invc[JJ];
    int tid = threadIdx.x;
    if (tid < JJ) invc[tid] = 1.f / fmaxf(gC[2][tid], 1e-30f);
    __syncthreads();
    int stride = gridDim.x * blockDim.x;
    for (int tok = blockIdx.x * blockDim.x + tid; tok < n; tok += stride) {
        int k = gt[tok];
        unsigned char bkt = 255;
        if (gPred[tok] == (unsigned char)k) {
            float4 a = *(const float4*)(gE + (size_t)tok * 8);
            float4 b4 = *(const float4*)(gE + (size_t)tok * 8 + 4);
            float e[8] = {a.x, a.y, a.z, a.w, b4.x, b4.y, b4.z, b4.w};
            float best = -1e30f; int bi = 0;
#pragma unroll
            for (int mm = 0; mm < 8; mm++) {
                float v = e[mm] * invc[k * 8 + mm];
                if (v > best) { best = v; bi = mm; }
            }
            bkt = (unsigned char)(k * 8 + bi);
        }
        gBucket[tok] = bkt;
    }
}

// ---------------- kernel 5: aggregation (register accumulators) --------------
#define AGG_SLICES 44
__global__ void __launch_bounds__(256) aggKernel(const float* __restrict__ X,
                                                 const float* __restrict__ g,
                                                 const float* __restrict__ b,
                                                 int n) {
    int l = threadIdx.x & 31;
    int wgid = blockIdx.x * 8 + (threadIdx.x >> 5);
    int bucket = wgid & 31;
    int slice = wgid >> 5;
    if (slice >= AGG_SLICES) return;

    int chunk = (n + AGG_SLICES - 1) / AGG_SLICES;
    int start = slice * chunk;
    int end = min(start + chunk, n);

    float gl[16], bl[16], acc[16];
#pragma unroll
    for (int i = 0; i < 16; i++) {
        gl[i] = g[l + 32 * i];
        bl[i] = b[l + 32 * i];
        acc[i] = 0.f;
    }
    int cnt = 0;

    for (int t0 = start; t0 < end; t0 += 32) {
        int tok = t0 + l;
        int myb = (tok < end) ? (int)gBucket[tok] : -1;
        unsigned mask = __ballot_sync(0xffffffffu, myb == bucket);
        cnt += __popc(mask);
        while (mask) {
            int bit = __ffs(mask) - 1;
            mask &= mask - 1;
            int th = t0 + bit;
            float4 abc = gABC[th];
            const float* x = X + (size_t)th * DD;
#pragma unroll
            for (int i = 0; i < 16; i++) {
                acc[i] += fmaf(abc.x * gl[i], x[l + 32 * i],
                               fmaf(abc.y, gl[i], abc.z * bl[i]));
            }
        }
    }
#pragma unroll
    for (int i = 0; i < 16; i++)
        if (acc[i] != 0.f) atomicAdd(&gF[bucket * DD + l + 32 * i], acc[i]);
    if (l == 0 && cnt > 0) atomicAdd(&gNcnt[bucket], (float)cnt);
}

// ---------------- kernel 6: finalize new prototypes ---------------------------
__global__ void finalKernel(float* __restrict__ outp) {
    int tid = threadIdx.x;
    int w = tid >> 5, l = tid & 31;
    int k = w >> 3;

    float nj = gNcnt[w];
    float nsum = 0.f;
#pragma unroll
    for (int mm = 0; mm < 8; mm++) nsum += gNcnt[k * 8 + mm];
    bool valid = (nj != 0.f) && (gBcnt[k] > 0.f) && (nsum > 0.f);

    float v[16];
    float ss = 0.f;
#pragma unroll
    for (int i = 0; i < 16; i++) {
        v[i] = gF[w * DD + l + 32 * i];
        ss += v[i] * v[i];
    }
#pragma unroll
    for (int o = 16; o > 0; o >>= 1) ss += __shfl_xor_sync(0xffffffffu, ss, o);
    float inv = 1.f / fmaxf(sqrtf(ss), 1e-12f);

    float out[16];
    float ss2 = 0.f;
#pragma unroll
    for (int i = 0; i < 16; i++) {
        float fn = v[i] * inv;
        float base = gPN[w * DD + l + 32 * i];
        float r = valid ? (GAMMA_M * base + (1.f - GAMMA_M) * fn) : base;
        out[i] = r;
        ss2 += r * r;
    }
#pragma unroll
    for (int o = 16; o > 0; o >>= 1) ss2 += __shfl_xor_sync(0xffffffffu, ss2, o);
    float inv2 = 1.f / fmaxf(sqrtf(ss2), 1e-12f);
#pragma unroll
    for (int i = 0; i < 16; i++)
        outp[w * DD + l + 32 * i] = out[i] * inv2;
}

// ---------------- launch ------------------------------------------------------
extern "C" void kernel_launch(void* const* d_in, const int* in_sizes, int n_in,
                              void* d_out, int out_size) {
    const float* feats  = (const float*)d_in[0];
    const float* ln_g   = (const float*)d_in[1];
    const float* ln_b   = (const float*)d_in[2];
    const float* mg     = (const float*)d_in[3];
    const float* mb     = (const float*)d_in[4];
    const float* protos = (const float*)d_in[5];
    const int*   gt     = (const int*)d_in[6];

    int n = in_sizes[0] / DD;
    float* outseg = (float*)d_out;
    float* outp   = (float*)d_out + (size_t)(out_size - JJ * DD);

    cudaFuncSetAttribute(fusedKernel, cudaFuncAttributeMaxDynamicSharedMemorySize, DSM_BYTES);

    initKernel<<<1, 1024>>>(protos, ln_g, ln_b);
    fusedKernel<<<(n + 127) / 128, 256, DSM_BYTES>>>(feats, gt, mg, mb, outseg, n);
    sinkIterKernel<<<64, 512>>>(gt, n, 0, 1);
    sinkIterKernel<<<64, 512>>>(gt, n, 1, 2);
    bucketKernel<<<256, 256>>>(gt, n);
    aggKernel<<<(32 * AGG_SLICES + 7) / 8, 256>>>(feats, ln_g, ln_b, n);
    finalKernel<<<1, 1024>>>(outp);
}